// round 7
// baseline (speedup 1.0000x reference)
#include <cuda_runtime.h>
#include <cuda_bf16.h>

#define N_STEPS   256
#define N_LORS    65536
#define IMG_ELEMS (128*128*128)

// Correctly-rounded reciprocal of 2.34375 (compile-time, round-to-nearest).
#define RCP_VOX (1.0f / 2.34375f)
#define VOX     2.34375f

// div.rn(x, VOX) via correctly-rounded reciprocal + ONE Markstein FMA step.
// q0 = RN(x*r) is within ~1 ulp; the fma-residual refinement brings the
// result within 0.5001 ulp of the true quotient, so floor() of it matches
// floor(div.rn) except with probability ~1e-9 per operand (negligible over
// 150M coords). Saves 2 FMAs per coordinate vs the 2-step version.
__device__ __forceinline__ float div_vox(float x) {
    float q = __fmul_rn(x, RCP_VOX);
    q = __fmaf_rn(__fmaf_rn(-VOX, q, x), RCP_VOX, q);
    return q;
}

// ---------------------------------------------------------------------------
// Trace kernel: warp-per-LOR. Iteration it covers steps [32*it, 32*it+32)
// with lane = step (consecutive). Index math matches the jax reference
// bit-for-bit (separate mul/add, correctly-rounded division).
//   Forward: 8 independent gathers (HW merges same-address lanes).
//   Backward: contiguous same-voxel runs aggregated via shfl/ballot; one
//             atomic (RED) per run from the head lane.
// ---------------------------------------------------------------------------
__global__ __launch_bounds__(256)
void trace_kernel(const float* __restrict__ img,
                  const float* __restrict__ xl,
                  const float* __restrict__ yl,
                  const float* __restrict__ zl,
                  float* __restrict__ acc) {
    const int warp = blockIdx.x * (blockDim.x >> 5) + (threadIdx.x >> 5);
    const int lane = threadIdx.x & 31;
    const int set  = warp >> 16;          // 0,1,2
    const int lor  = warp & (N_LORS - 1);

    const float* lors = (set == 0) ? xl : (set == 1) ? yl : zl;
    const float* L = lors + 7 * lor;

    const float p1x = __ldg(L + 0), p1y = __ldg(L + 1), p1z = __ldg(L + 2);
    const float dx = __fadd_rn(__ldg(L + 3), -p1x);
    const float dy = __fadd_rn(__ldg(L + 4), -p1y);
    const float dz = __fadd_rn(__ldg(L + 5), -p1z);
    const float meas = __ldg(L + 6);
    const float seg = sqrtf(dx*dx + dy*dy + dz*dz) * (1.0f / N_STEPS);

    int flats[8];

    // t for this lane's step in iteration 0. Incrementing by 0.125f is EXACT
    // (all t are multiples of 2^-9), identical to (st+0.5)/256.
    float t = ((float)lane + 0.5f) * (1.0f / N_STEPS);

    #pragma unroll
    for (int it = 0; it < 8; it++) {
        // pos = p1 + t*d, separate mul/add (no contraction) to match jax
        const float px = __fadd_rn(p1x, __fmul_rn(t, dx));
        const float py = __fadd_rn(p1y, __fmul_rn(t, dy));
        const float pz = __fadd_rn(p1z, __fmul_rn(t, dz));
        const int ix = __float2int_rd(div_vox(__fadd_rn(px, 150.0f)));
        const int iy = __float2int_rd(div_vox(__fadd_rn(py, 150.0f)));
        const int iz = __float2int_rd(div_vox(__fadd_rn(pz, 150.0f)));
        const bool inb = ((unsigned)ix < 128u) & ((unsigned)iy < 128u) &
                         ((unsigned)iz < 128u);
        flats[it] = inb ? (((ix << 7) + iy) << 7) + iz : -1;
        t = __fadd_rn(t, 0.125f);
    }

    // ---- forward projection: 8 independent gathers ----
    float s = 0.f;
    #pragma unroll
    for (int it = 0; it < 8; it++) {
        const int f = flats[it];
        s += (f >= 0) ? __ldg(img + f) : 0.f;
    }

    #pragma unroll
    for (int o = 16; o > 0; o >>= 1)
        s += __shfl_xor_sync(0xffffffffu, s, o);

    const float proj = s * seg;
    const float w = meas / (proj + 1e-8f) * seg;   // ratio * seg

    // ---- backprojection: one atomic per contiguous same-voxel run ----
    #pragma unroll
    for (int it = 0; it < 8; it++) {
        const int f = flats[it];
        const int fprev = __shfl_up_sync(0xffffffffu, f, 1);
        const bool head = (lane == 0) || (f != fprev);
        const unsigned b = __ballot_sync(0xffffffffu, head);
        if (head && f >= 0) {
            const unsigned rest = (b >> lane) >> 1;   // heads after me
            const int cnt = rest ? __ffs(rest) : (32 - lane);
            atomicAdd(acc + f, w * (float)cnt);
        }
    }
}

// ---------------------------------------------------------------------------
// Finalize: out = image / (eff + eps) * acc   (in-place on d_out)
// ---------------------------------------------------------------------------
__global__ void finalize_kernel(const float4* __restrict__ img,
                                const float4* __restrict__ eff,
                                float4* __restrict__ out) {
    int i = blockIdx.x * blockDim.x + threadIdx.x;
    float4 a = img[i], e = eff[i], o = out[i];
    o.x = a.x / (e.x + 1e-8f) * o.x;
    o.y = a.y / (e.y + 1e-8f) * o.y;
    o.z = a.z / (e.z + 1e-8f) * o.z;
    o.w = a.w / (e.w + 1e-8f) * o.w;
    out[i] = o;
}

extern "C" void kernel_launch(void* const* d_in, const int* in_sizes, int n_in,
                              void* d_out, int out_size) {
    const float* image = (const float*)d_in[0];
    const float* eff   = (const float*)d_in[1];
    const float* xl    = (const float*)d_in[2];
    const float* yl    = (const float*)d_in[3];
    const float* zl    = (const float*)d_in[4];
    float* out = (float*)d_out;

    // zero the accumulator (d_out) — capturable, no allocation
    cudaMemsetAsync(out, 0, IMG_ELEMS * sizeof(float), 0);

    const int total_warps = 3 * N_LORS;          // one warp per LOR
    trace_kernel<<<total_warps / 8, 256>>>(image, xl, yl, zl, out);

    finalize_kernel<<<IMG_ELEMS / 4 / 256, 256>>>((const float4*)image,
                                                  (const float4*)eff,
                                                  (float4*)out);
}